// round 1
// baseline (speedup 1.0000x reference)
#include <cuda_runtime.h>

#define B 64
#define NEG_BIG (-3.402823466e38f)

// ---------------- scratch (device globals; no allocation) ----------------
__device__ float g_t1[B * 128 * 128];
__device__ float g_t2[B * 64 * 64];
__device__ float g_t3[B * 64 * 64];
__device__ float g_t4[B * 32 * 32];
__device__ float g_t5[B * 32 * 32];
__device__ float g_t6[B * 16 * 16];
__device__ float g_fc[B * 1024];
__device__ float g_stats[6 * B * 2];   // [layer][sample][{sum,sumsq}]

// ---------------- init: zero the stats accumulators ----------------
__global__ void init_kernel() {
    int i = threadIdx.x;
    if (i < 6 * B * 2) g_stats[i] = 0.f;
}

// ---------------- locally-connected layer ----------------
// Computes out = relu(LC(in')) where in' is the (optionally LN'd + pooled)
// previous activation, and accumulates per-sample sum/sumsq of `out` into
// stats_out for the NEXT layer's LayerNorm.
//
// Block: TILE x TILE output positions, loops over all 64 samples in groups.
// Weights for this thread's output position live in registers (reused 64x).
template <int HOUT, int K, int TILE, bool RAW, bool POOL>
__global__ __launch_bounds__(256) void lc_kernel(
    const float* __restrict__ in,
    const float* __restrict__ w,
    const float* __restrict__ bias,
    const float* __restrict__ gp,        // prev-layer LN gamma (unused if RAW)
    const float* __restrict__ bp,        // prev-layer LN beta
    const float* __restrict__ stats_in,  // prev-layer [B][2] (unused if RAW)
    float* __restrict__ out,
    float* __restrict__ stats_out)
{
    constexpr int PAD = K / 2;
    constexpr int P = TILE + K - 1;
    constexpr int NOUT = TILE * TILE;
    constexpr int SGROUP = 256 / NOUT;
    constexpr int WIDTH = (NOUT < 32) ? NOUT : 32;
    constexpr int HPREV = POOL ? HOUT * 2 : HOUT;   // stored prev plane size
    const float INVN = 1.f / (float)(HPREV * HPREV);

    __shared__ float xs[SGROUP][P][P];
    __shared__ float musig[B][2];
    __shared__ float sacc[B][2];

    const int tid = threadIdx.x;
    const int nbx = HOUT / TILE;
    const int bi = blockIdx.x / nbx;
    const int bj = blockIdx.x % nbx;
    const int s_local = tid / NOUT;
    const int ol = tid % NOUT;
    const int oi = ol / TILE, oj = ol % TILE;
    const int gi = bi * TILE + oi, gj = bj * TILE + oj;

    // per-thread weights + bias in registers
    float wreg[K * K];
#pragma unroll
    for (int t = 0; t < K * K; t++) wreg[t] = w[(gi * HOUT + gj) * K * K + t];
    const float breg = bias[gi * HOUT + gj];

    if (tid < B) {
        sacc[tid][0] = 0.f;
        sacc[tid][1] = 0.f;
        if (!RAW) {
            float s0 = stats_in[2 * tid];
            float s1 = stats_in[2 * tid + 1];
            float mu = s0 * INVN;
            float var = s1 * INVN - mu * mu;
            musig[tid][0] = mu;
            musig[tid][1] = rsqrtf(var + 1e-5f);
        }
    }
    __syncthreads();

    for (int sb = 0; sb < B; sb += SGROUP) {
        // ---- stage input patches (apply LN / LN+pool on the fly) ----
        for (int idx = tid; idx < SGROUP * P * P; idx += 256) {
            int sl = idx / (P * P);
            int rem = idx % (P * P);
            int pr = rem / P, pc = rem % P;
            int s = sb + sl;
            int r = bi * TILE + pr - PAD;
            int c = bj * TILE + pc - PAD;
            float v = 0.f;
            if (r >= 0 && r < HOUT && c >= 0 && c < HOUT) {
                if (RAW) {
                    v = in[(s * HOUT + r) * HOUT + c];
                } else {
                    float mu = musig[s][0], rs = musig[s][1];
                    if (POOL) {
                        v = NEG_BIG;
#pragma unroll
                        for (int dr = 0; dr < 2; dr++)
#pragma unroll
                            for (int dc = 0; dc < 2; dc++) {
                                int rr = 2 * r + dr, cc = 2 * c + dc;
                                float t = in[(s * HPREV + rr) * HPREV + cc];
                                float n = (t - mu) * rs * gp[rr * HPREV + cc] + bp[rr * HPREV + cc];
                                v = fmaxf(v, n);
                            }
                    } else {
                        float t = in[(s * HOUT + r) * HOUT + c];
                        v = (t - mu) * rs * gp[r * HOUT + c] + bp[r * HOUT + c];
                    }
                }
            }
            xs[sl][pr][pc] = v;
        }
        __syncthreads();

        // ---- compute this thread's output ----
        float acc = breg;
#pragma unroll
        for (int r = 0; r < K; r++)
#pragma unroll
            for (int c = 0; c < K; c++)
                acc = fmaf(xs[s_local][oi + r][oj + c], wreg[r * K + c], acc);
        acc = fmaxf(acc, 0.f);
        const int s = sb + s_local;
        out[(s * HOUT + gi) * HOUT + gj] = acc;

        // ---- per-sample stats: segment shuffle-reduce + shared atomic ----
        float lsum = acc, lsq = acc * acc;
#pragma unroll
        for (int off = WIDTH / 2; off > 0; off >>= 1) {
            lsum += __shfl_xor_sync(0xffffffffu, lsum, off, WIDTH);
            lsq  += __shfl_xor_sync(0xffffffffu, lsq,  off, WIDTH);
        }
        if ((tid & (WIDTH - 1)) == 0) {
            atomicAdd(&sacc[s][0], lsum);
            atomicAdd(&sacc[s][1], lsq);
        }
        __syncthreads();
    }

    if (tid < B) {
        atomicAdd(&stats_out[2 * tid], sacc[tid][0]);
        atomicAdd(&stats_out[2 * tid + 1], sacc[tid][1]);
    }
}

// ---------------- FC: LN6(t6) flattened [64,256] @ fcw^T + fcb ----------------
// grid 64 blocks x 16 outputs; 256 threads = 16 outputs x 16 samples.
__global__ __launch_bounds__(256) void fc_kernel(
    const float* __restrict__ fcw, const float* __restrict__ fcb,
    const float* __restrict__ g6, const float* __restrict__ be6)
{
    __shared__ float in_sh[16][257];
    __shared__ float musig[B][2];

    const int tid = threadIdx.x;
    const int o = blockIdx.x * 16 + (tid % 16);
    const int s_local = tid / 16;

    if (tid < B) {
        float s0 = g_stats[5 * B * 2 + 2 * tid];
        float s1 = g_stats[5 * B * 2 + 2 * tid + 1];
        float mu = s0 * (1.f / 256.f);
        float var = s1 * (1.f / 256.f) - mu * mu;
        musig[tid][0] = mu;
        musig[tid][1] = rsqrtf(var + 1e-5f);
    }
    __syncthreads();

    const float bo = fcb[o];
    for (int sg = 0; sg < B; sg += 16) {
        for (int idx = tid; idx < 16 * 256; idx += 256) {
            int sl = idx >> 8;
            int c = idx & 255;
            int s = sg + sl;
            float t = g_t6[s * 256 + c];
            in_sh[sl][c] = (t - musig[s][0]) * musig[s][1] * g6[c] + be6[c];
        }
        __syncthreads();

        float acc = bo;
#pragma unroll 8
        for (int c = 0; c < 256; c++)
            acc = fmaf(in_sh[s_local][c], fcw[o * 256 + c], acc);
        g_fc[(sg + s_local) * 1024 + o] = acc;
        __syncthreads();
    }
}

// ---------------- softmax over the 1024 logits per sample ----------------
__global__ __launch_bounds__(256) void softmax_kernel(float* __restrict__ out)
{
    __shared__ float red[256];
    const int s = blockIdx.x, tid = threadIdx.x;

    float v[4];
    float m = NEG_BIG;
#pragma unroll
    for (int k = 0; k < 4; k++) {
        v[k] = g_fc[s * 1024 + tid + 256 * k];
        m = fmaxf(m, v[k]);
    }
    red[tid] = m;
    __syncthreads();
    for (int off = 128; off > 0; off >>= 1) {
        if (tid < off) red[tid] = fmaxf(red[tid], red[tid + off]);
        __syncthreads();
    }
    m = red[0];
    __syncthreads();

    float sum = 0.f;
#pragma unroll
    for (int k = 0; k < 4; k++) {
        v[k] = expf(v[k] - m);
        sum += v[k];
    }
    red[tid] = sum;
    __syncthreads();
    for (int off = 128; off > 0; off >>= 1) {
        if (tid < off) red[tid] += red[tid + off];
        __syncthreads();
    }
    const float inv = 1.f / red[0];
#pragma unroll
    for (int k = 0; k < 4; k++)
        out[s * 1024 + tid + 256 * k] = v[k] * inv;
}

// ---------------- launch ----------------
extern "C" void kernel_launch(void* const* d_in, const int* in_sizes, int n_in,
                              void* d_out, int out_size)
{
    const float* X = (const float*)d_in[0];
    const float* W[6];
    const float* Bi[6];
    const float* G[6];
    const float* Be[6];
    for (int i = 0; i < 6; i++) {
        W[i]  = (const float*)d_in[1 + 4 * i];
        Bi[i] = (const float*)d_in[2 + 4 * i];
        G[i]  = (const float*)d_in[3 + 4 * i];
        Be[i] = (const float*)d_in[4 + 4 * i];
    }
    const float* FCW = (const float*)d_in[25];
    const float* FCB = (const float*)d_in[26];

    float *t1, *t2, *t3, *t4, *t5, *t6, *st;
    cudaGetSymbolAddress((void**)&t1, g_t1);
    cudaGetSymbolAddress((void**)&t2, g_t2);
    cudaGetSymbolAddress((void**)&t3, g_t3);
    cudaGetSymbolAddress((void**)&t4, g_t4);
    cudaGetSymbolAddress((void**)&t5, g_t5);
    cudaGetSymbolAddress((void**)&t6, g_t6);
    cudaGetSymbolAddress((void**)&st, g_stats);

    init_kernel<<<1, 768>>>();

    // L1: raw x -> LC 7x7 -> t1, stats[0]
    lc_kernel<128, 7, 8, true, false><<<256, 256>>>(X, W[0], Bi[0], nullptr, nullptr, nullptr,
                                                    t1, st + 0 * B * 2);
    // L2: LN1+pool(t1) -> LC 5x5 -> t2, stats[1]
    lc_kernel<64, 5, 8, false, true><<<64, 256>>>(t1, W[1], Bi[1], G[0], Be[0], st + 0 * B * 2,
                                                  t2, st + 1 * B * 2);
    // L3: LN2(t2) -> LC 5x5 -> t3, stats[2]
    lc_kernel<64, 5, 8, false, false><<<64, 256>>>(t2, W[2], Bi[2], G[1], Be[1], st + 1 * B * 2,
                                                   t3, st + 2 * B * 2);
    // L4: LN3+pool(t3) -> LC 3x3 -> t4, stats[3]
    lc_kernel<32, 3, 4, false, true><<<64, 256>>>(t3, W[3], Bi[3], G[2], Be[2], st + 2 * B * 2,
                                                  t4, st + 3 * B * 2);
    // L5: LN4(t4) -> LC 3x3 -> t5, stats[4]
    lc_kernel<32, 3, 4, false, false><<<64, 256>>>(t4, W[4], Bi[4], G[3], Be[3], st + 3 * B * 2,
                                                   t5, st + 4 * B * 2);
    // L6: LN5+pool(t5) -> LC 3x3 -> t6, stats[5]
    lc_kernel<16, 3, 2, false, true><<<64, 256>>>(t5, W[5], Bi[5], G[4], Be[4], st + 4 * B * 2,
                                                  t6, st + 5 * B * 2);

    fc_kernel<<<64, 256>>>(FCW, FCB, G[5], Be[5]);
    softmax_kernel<<<64, 256>>>((float*)d_out);
}

// round 2
// speedup vs baseline: 1.8541x; 1.8541x over previous
#include <cuda_runtime.h>

#define B 64
#define NEG_BIG (-3.402823466e38f)

// ---------------- scratch (device globals; no allocation) ----------------
__device__ float g_t1[B * 128 * 128];
__device__ float g_t2[B * 64 * 64];
__device__ float g_t3[B * 64 * 64];
__device__ float g_t4[B * 32 * 32];
__device__ float g_t5[B * 32 * 32];
__device__ float g_t6[B * 16 * 16];
__device__ float g_fc[B * 1024];
__device__ float g_stats[6 * B * 2];   // [layer][sample][{sum,sumsq}]

// ---------------- init: zero the stats accumulators ----------------
__global__ void init_kernel() {
    int i = threadIdx.x;
    if (i < 6 * B * 2) g_stats[i] = 0.f;
}

// ---------------- locally-connected layer ----------------
// out = relu(LC(in')) where in' is the (optionally LN'd + pooled) previous
// activation; accumulates per-sample sum/sumsq of out into stats_out.
//
// Grid: (spatial tiles, SPLIT sample groups). Each block: TILE x TILE output
// positions x SGROUP samples per iteration, B/SPLIT samples total.
template <int HOUT, int K, int TILE, int SPLIT, bool RAW, bool POOL>
__global__ __launch_bounds__(256) void lc_kernel(
    const float* __restrict__ in,
    const float* __restrict__ w,
    const float* __restrict__ bias,
    const float* __restrict__ gp,        // prev-layer LN gamma (unused if RAW)
    const float* __restrict__ bp,        // prev-layer LN beta
    const float* __restrict__ stats_in,  // prev-layer [B][2] (unused if RAW)
    float* __restrict__ out,
    float* __restrict__ stats_out)
{
    constexpr int PAD = K / 2;
    constexpr int P = TILE + K - 1;
    constexpr int NOUT = TILE * TILE;
    constexpr int SGROUP = 256 / NOUT;
    constexpr int SPB = B / SPLIT;                 // samples per block
    constexpr int WIDTH = (NOUT < 32) ? NOUT : 32;
    constexpr int HPREV = POOL ? HOUT * 2 : HOUT;  // stored prev plane size
    const float INVN = 1.f / (float)(HPREV * HPREV);

    __shared__ float xs[SGROUP][P][P];
    __shared__ float musig[B][2];
    __shared__ float sacc[SPB][2];

    const int tid = threadIdx.x;
    const int nbx = HOUT / TILE;
    const int bi = blockIdx.x / nbx;
    const int bj = blockIdx.x % nbx;
    const int s0 = blockIdx.y * SPB;
    const int s_local = tid / NOUT;
    const int ol = tid % NOUT;
    const int oi = ol / TILE, oj = ol % TILE;
    const int gi = bi * TILE + oi, gj = bj * TILE + oj;

    // per-thread weights + bias in registers (reused for SPB samples)
    float wreg[K * K];
#pragma unroll
    for (int t = 0; t < K * K; t++) wreg[t] = w[(gi * HOUT + gj) * K * K + t];
    const float breg = bias[gi * HOUT + gj];

    if (tid < SPB) { sacc[tid][0] = 0.f; sacc[tid][1] = 0.f; }
    if (!RAW && tid < B) {
        float ss0 = stats_in[2 * tid];
        float ss1 = stats_in[2 * tid + 1];
        float mu = ss0 * INVN;
        float var = ss1 * INVN - mu * mu;
        musig[tid][0] = mu;
        musig[tid][1] = rsqrtf(var + 1e-5f);
    }
    __syncthreads();

#pragma unroll
    for (int sb = 0; sb < SPB; sb += SGROUP) {
        // ---- stage input patches (apply LN / LN+pool on the fly) ----
        for (int idx = tid; idx < SGROUP * P * P; idx += 256) {
            int sl = idx / (P * P);
            int rem = idx % (P * P);
            int pr = rem / P, pc = rem % P;
            int s = s0 + sb + sl;
            int r = bi * TILE + pr - PAD;
            int c = bj * TILE + pc - PAD;
            float v = 0.f;
            if (r >= 0 && r < HOUT && c >= 0 && c < HOUT) {
                if (RAW) {
                    v = in[(s * HOUT + r) * HOUT + c];
                } else {
                    float mu = musig[s][0], rs = musig[s][1];
                    if (POOL) {
                        v = NEG_BIG;
#pragma unroll
                        for (int dr = 0; dr < 2; dr++)
#pragma unroll
                            for (int dc = 0; dc < 2; dc++) {
                                int rr = 2 * r + dr, cc = 2 * c + dc;
                                float t = in[(s * HPREV + rr) * HPREV + cc];
                                float n = (t - mu) * rs * gp[rr * HPREV + cc] + bp[rr * HPREV + cc];
                                v = fmaxf(v, n);
                            }
                    } else {
                        float t = in[(s * HOUT + r) * HOUT + c];
                        v = (t - mu) * rs * gp[r * HOUT + c] + bp[r * HOUT + c];
                    }
                }
            }
            xs[sl][pr][pc] = v;
        }
        __syncthreads();

        // ---- compute this thread's output ----
        float acc = breg;
#pragma unroll
        for (int r = 0; r < K; r++)
#pragma unroll
            for (int c = 0; c < K; c++)
                acc = fmaf(xs[s_local][oi + r][oj + c], wreg[r * K + c], acc);
        acc = fmaxf(acc, 0.f);
        const int s = s0 + sb + s_local;
        out[(s * HOUT + gi) * HOUT + gj] = acc;

        // ---- per-sample stats: segment shuffle-reduce + shared atomic ----
        float lsum = acc, lsq = acc * acc;
#pragma unroll
        for (int off = WIDTH / 2; off > 0; off >>= 1) {
            lsum += __shfl_xor_sync(0xffffffffu, lsum, off, WIDTH);
            lsq  += __shfl_xor_sync(0xffffffffu, lsq,  off, WIDTH);
        }
        if ((tid & (WIDTH - 1)) == 0) {
            atomicAdd(&sacc[sb + s_local][0], lsum);
            atomicAdd(&sacc[sb + s_local][1], lsq);
        }
        __syncthreads();
    }

    if (tid < SPB) {
        atomicAdd(&stats_out[2 * (s0 + tid)], sacc[tid][0]);
        atomicAdd(&stats_out[2 * (s0 + tid) + 1], sacc[tid][1]);
    }
}

// ---------------- FC: LN6(t6) flattened [64,256] @ fcw^T + fcb ----------------
// grid (64, 4): block = 16 outputs x 16 samples, single pass.
__global__ __launch_bounds__(256) void fc_kernel(
    const float* __restrict__ fcw, const float* __restrict__ fcb,
    const float* __restrict__ g6, const float* __restrict__ be6)
{
    __shared__ float in_sh[16][257];
    __shared__ float musig[B][2];

    const int tid = threadIdx.x;
    const int o = blockIdx.x * 16 + (tid % 16);
    const int s_local = tid / 16;
    const int s0 = blockIdx.y * 16;

    if (tid < B) {
        float ss0 = g_stats[5 * B * 2 + 2 * tid];
        float ss1 = g_stats[5 * B * 2 + 2 * tid + 1];
        float mu = ss0 * (1.f / 256.f);
        float var = ss1 * (1.f / 256.f) - mu * mu;
        musig[tid][0] = mu;
        musig[tid][1] = rsqrtf(var + 1e-5f);
    }
    __syncthreads();

    for (int idx = tid; idx < 16 * 256; idx += 256) {
        int sl = idx >> 8;
        int c = idx & 255;
        int s = s0 + sl;
        float t = g_t6[s * 256 + c];
        in_sh[sl][c] = (t - musig[s][0]) * musig[s][1] * g6[c] + be6[c];
    }
    __syncthreads();

    float acc = fcb[o];
    const float4* wrow = (const float4*)(fcw + o * 256);
#pragma unroll 8
    for (int c4 = 0; c4 < 64; c4++) {
        float4 wv = wrow[c4];
        acc = fmaf(in_sh[s_local][4 * c4 + 0], wv.x, acc);
        acc = fmaf(in_sh[s_local][4 * c4 + 1], wv.y, acc);
        acc = fmaf(in_sh[s_local][4 * c4 + 2], wv.z, acc);
        acc = fmaf(in_sh[s_local][4 * c4 + 3], wv.w, acc);
    }
    g_fc[(s0 + s_local) * 1024 + o] = acc;
}

// ---------------- softmax over the 1024 logits per sample ----------------
__global__ __launch_bounds__(256) void softmax_kernel(float* __restrict__ out)
{
    __shared__ float red[256];
    const int s = blockIdx.x, tid = threadIdx.x;

    float v[4];
    float m = NEG_BIG;
#pragma unroll
    for (int k = 0; k < 4; k++) {
        v[k] = g_fc[s * 1024 + tid + 256 * k];
        m = fmaxf(m, v[k]);
    }
    red[tid] = m;
    __syncthreads();
    for (int off = 128; off > 0; off >>= 1) {
        if (tid < off) red[tid] = fmaxf(red[tid], red[tid + off]);
        __syncthreads();
    }
    m = red[0];
    __syncthreads();

    float sum = 0.f;
#pragma unroll
    for (int k = 0; k < 4; k++) {
        v[k] = expf(v[k] - m);
        sum += v[k];
    }
    red[tid] = sum;
    __syncthreads();
    for (int off = 128; off > 0; off >>= 1) {
        if (tid < off) red[tid] += red[tid + off];
        __syncthreads();
    }
    const float inv = 1.f / red[0];
#pragma unroll
    for (int k = 0; k < 4; k++)
        out[s * 1024 + tid + 256 * k] = v[k] * inv;
}

// ---------------- launch ----------------
extern "C" void kernel_launch(void* const* d_in, const int* in_sizes, int n_in,
                              void* d_out, int out_size)
{
    const float* X = (const float*)d_in[0];
    const float* W[6];
    const float* Bi[6];
    const float* G[6];
    const float* Be[6];
    for (int i = 0; i < 6; i++) {
        W[i]  = (const float*)d_in[1 + 4 * i];
        Bi[i] = (const float*)d_in[2 + 4 * i];
        G[i]  = (const float*)d_in[3 + 4 * i];
        Be[i] = (const float*)d_in[4 + 4 * i];
    }
    const float* FCW = (const float*)d_in[25];
    const float* FCB = (const float*)d_in[26];

    float *t1, *t2, *t3, *t4, *t5, *t6, *st;
    cudaGetSymbolAddress((void**)&t1, g_t1);
    cudaGetSymbolAddress((void**)&t2, g_t2);
    cudaGetSymbolAddress((void**)&t3, g_t3);
    cudaGetSymbolAddress((void**)&t4, g_t4);
    cudaGetSymbolAddress((void**)&t5, g_t5);
    cudaGetSymbolAddress((void**)&t6, g_t6);
    cudaGetSymbolAddress((void**)&st, g_stats);

    init_kernel<<<1, 768>>>();

    // L1: raw x -> LC 7x7 -> t1, stats[0]        grid (256,8), 2 iters
    lc_kernel<128, 7, 8, 8, true, false><<<dim3(256, 8), 256>>>(
        X, W[0], Bi[0], nullptr, nullptr, nullptr, t1, st + 0 * B * 2);
    // L2: LN1+pool(t1) -> LC 5x5 -> t2           grid (64,16), 1 iter
    lc_kernel<64, 5, 8, 16, false, true><<<dim3(64, 16), 256>>>(
        t1, W[1], Bi[1], G[0], Be[0], st + 0 * B * 2, t2, st + 1 * B * 2);
    // L3: LN2(t2) -> LC 5x5 -> t3                grid (64,16), 1 iter
    lc_kernel<64, 5, 8, 16, false, false><<<dim3(64, 16), 256>>>(
        t2, W[2], Bi[2], G[1], Be[1], st + 1 * B * 2, t3, st + 2 * B * 2);
    // L4: LN3+pool(t3) -> LC 3x3 -> t4           grid (64,4), 1 iter
    lc_kernel<32, 3, 4, 4, false, true><<<dim3(64, 4), 256>>>(
        t3, W[3], Bi[3], G[2], Be[2], st + 2 * B * 2, t4, st + 3 * B * 2);
    // L5: LN4(t4) -> LC 3x3 -> t5                grid (64,4), 1 iter
    lc_kernel<32, 3, 4, 4, false, false><<<dim3(64, 4), 256>>>(
        t4, W[4], Bi[4], G[3], Be[3], st + 3 * B * 2, t5, st + 4 * B * 2);
    // L6: LN5+pool(t5) -> LC 3x3 -> t6           grid (64,1), 1 iter
    lc_kernel<16, 3, 2, 1, false, true><<<dim3(64, 1), 256>>>(
        t5, W[5], Bi[5], G[4], Be[4], st + 4 * B * 2, t6, st + 5 * B * 2);

    fc_kernel<<<dim3(64, 4), 256>>>(FCW, FCB, G[5], Be[5]);
    softmax_kernel<<<64, 256>>>((float*)d_out);
}

// round 3
// speedup vs baseline: 2.4157x; 1.3029x over previous
#include <cuda_runtime.h>

#define B 64
#define NEG_BIG (-3.402823466e38f)

// ---------------- scratch (device globals; no allocation) ----------------
__device__ float g_t1[B * 128 * 128];
__device__ float g_t6[B * 256];          // LN6-applied FC input
__device__ float g_fcp[2][B * 1024];     // FC partials (k-split halves)

// =====================================================================
// Kernel A: L1 locally-connected 7x7 on raw x -> relu -> g_t1
// grid (256, 8): 256 tiles (16x16 grid of 8x8), 8 sample-splits of 8.
// Weights staged coalesced into smem, hoisted to regs, reused x8 samples.
// =====================================================================
__global__ __launch_bounds__(256) void l1_kernel(
    const float* __restrict__ x, const float* __restrict__ w,
    const float* __restrict__ bias, float* __restrict__ out)
{
    __shared__ float wsh[64 * 49];
    __shared__ float bsh[64];
    __shared__ float xs[4][14][14];

    const int tid = threadIdx.x;
    const int bi = blockIdx.x >> 4, bj = blockIdx.x & 15;
    const int s0 = blockIdx.y * 8;

    // stage weights: 8 contiguous runs of 392 floats (one output row each)
    for (int idx = tid; idx < 64 * 49; idx += 256) {
        int rr = idx / 392;
        int rem = idx % 392;
        wsh[rr * 392 + rem] = w[((bi * 8 + rr) * 128 + bj * 8) * 49 + rem];
    }
    if (tid < 64) bsh[tid] = bias[(bi * 8 + tid / 8) * 128 + bj * 8 + (tid & 7)];
    __syncthreads();

    const int sl = tid >> 6;          // 0..3 sample-in-group
    const int ol = tid & 63;
    const int oi = ol >> 3, oj = ol & 7;

    float wr[49];
#pragma unroll
    for (int t = 0; t < 49; t++) wr[t] = wsh[ol * 49 + t];
    const float br = bsh[ol];

    for (int it = 0; it < 2; it++) {
        const int sbase = s0 + it * 4;
        __syncthreads();
        for (int idx = tid; idx < 4 * 196; idx += 256) {
            int s = idx / 196;
            int rem = idx % 196;
            int pr = rem / 14, pc = rem % 14;
            int r = bi * 8 + pr - 3, c = bj * 8 + pc - 3;
            float v = 0.f;
            if (r >= 0 && r < 128 && c >= 0 && c < 128)
                v = x[((sbase + s) * 128 + r) * 128 + c];
            xs[s][pr][pc] = v;
        }
        __syncthreads();

        float acc = br;
#pragma unroll
        for (int r = 0; r < 7; r++)
#pragma unroll
            for (int c = 0; c < 7; c++)
                acc = fmaf(xs[sl][oi + r][oj + c], wr[r * 7 + c], acc);
        acc = fmaxf(acc, 0.f);
        out[((sbase + sl) * 128 + bi * 8 + oi) * 128 + bj * 8 + oj] = acc;
    }
}

// =====================================================================
// Kernel B: fused L2..L6 (+ all LayerNorms & pools), block-per-sample.
// 64 blocks x 512 threads. Dynamic smem:
//   IN  [68*68]  halo'd input plane (zero halo -> branch-free taps)
//   OUT [64*64]  raw relu output plane (for stats + LN/pool reads)
//   WS  [2*512*25] double-buffered weight stage
//   RED [34]     block-reduce scratch + broadcast mu/rsig
// =====================================================================
#define SM_IN   0
#define SM_OUT  (68 * 68)
#define SM_WS   (SM_OUT + 64 * 64)
#define SM_RED  (SM_WS + 2 * 512 * 25)
#define SM_TOT  (SM_RED + 34)

__device__ __forceinline__ void bred(float ls, float lq, float invn, float* RED)
{
#pragma unroll
    for (int o = 16; o > 0; o >>= 1) {
        ls += __shfl_xor_sync(0xffffffffu, ls, o);
        lq += __shfl_xor_sync(0xffffffffu, lq, o);
    }
    const int wid = threadIdx.x >> 5, lane = threadIdx.x & 31;
    if (lane == 0) { RED[wid] = ls; RED[16 + wid] = lq; }
    __syncthreads();
    if (threadIdx.x == 0) {
        float s = 0.f, q = 0.f;
#pragma unroll
        for (int i = 0; i < 16; i++) { s += RED[i]; q += RED[16 + i]; }
        float mu = s * invn;
        float var = q * invn - mu * mu;
        RED[32] = mu;
        RED[33] = rsqrtf(var + 1e-5f);
    }
    __syncthreads();
}

template <int HO, int KK, int STRIDE>
__device__ __forceinline__ void lc_layer(
    const float* IN, float* OUT, float* WS,
    const float* __restrict__ w, const float* __restrict__ bias,
    float& ls, float& lq)
{
    constexpr int NPOS = HO * HO;
    constexpr int NCH = (NPOS + 511) / 512;
    constexpr int KB = KK * KK;
    constexpr int WBUF = 512 * KB;

    {   // prefetch chunk 0
        int cnt0 = (NPOS < 512 ? NPOS : 512) * KB;
        const float4* s4 = (const float4*)w;
        float4* d4 = (float4*)WS;
        for (int i = threadIdx.x; i < cnt0 / 4; i += 512) d4[i] = s4[i];
    }
    for (int ch = 0; ch < NCH; ch++) {
        __syncthreads();
        if (ch + 1 < NCH) {   // prefetch next chunk into other buffer
            int base = (ch + 1) * 512;
            int rem = NPOS - base;
            int cnt = (rem < 512 ? rem : 512) * KB;
            const float4* s4 = (const float4*)(w + base * KB);
            float4* d4 = (float4*)(WS + ((ch + 1) & 1) * WBUF);
            for (int i = threadIdx.x; i < cnt / 4; i += 512) d4[i] = s4[i];
        }
        int p = ch * 512 + threadIdx.x;
        if (p < NPOS) {
            const float* wb = WS + (ch & 1) * WBUF + threadIdx.x * KB;
            float wr[KB];
#pragma unroll
            for (int t = 0; t < KB; t++) wr[t] = wb[t];
            int oi = p / HO, oj = p % HO;
            float acc = bias[p];
#pragma unroll
            for (int r = 0; r < KK; r++)
#pragma unroll
                for (int c = 0; c < KK; c++)
                    acc = fmaf(IN[(oi + r) * STRIDE + oj + c], wr[r * KK + c], acc);
            acc = fmaxf(acc, 0.f);
            OUT[p] = acc;
            ls += acc;
            lq += acc * acc;
        }
    }
    __syncthreads();
}

template <int HO, int PAD, int STRIDE>
__device__ __forceinline__ void ln_apply(
    const float* OUT, float* IN, const float* __restrict__ g,
    const float* __restrict__ be, float mu, float rs)
{
    for (int p = threadIdx.x; p < HO * HO; p += 512) {
        int i = p / HO, j = p % HO;
        IN[(i + PAD) * STRIDE + j + PAD] = (OUT[p] - mu) * rs * g[p] + be[p];
    }
}

template <int HO, int PAD, int STRIDE>
__device__ __forceinline__ void ln_pool(
    const float* OUT, float* IN, const float* __restrict__ g,
    const float* __restrict__ be, float mu, float rs)
{
    constexpr int H2 = HO * 2;
    for (int p = threadIdx.x; p < HO * HO; p += 512) {
        int i = p / HO, j = p % HO;
        float m = NEG_BIG;
#pragma unroll
        for (int dr = 0; dr < 2; dr++)
#pragma unroll
            for (int dc = 0; dc < 2; dc++) {
                int idx = (2 * i + dr) * H2 + 2 * j + dc;
                float t = OUT[idx];
                m = fmaxf(m, (t - mu) * rs * g[idx] + be[idx]);
            }
        IN[(i + PAD) * STRIDE + j + PAD] = m;
    }
}

__global__ __launch_bounds__(512) void fused_kernel(
    const float* __restrict__ w2, const float* __restrict__ b2,
    const float* __restrict__ w3, const float* __restrict__ b3,
    const float* __restrict__ w4, const float* __restrict__ b4,
    const float* __restrict__ w5, const float* __restrict__ b5,
    const float* __restrict__ w6, const float* __restrict__ b6,
    const float* __restrict__ g1, const float* __restrict__ be1,
    const float* __restrict__ g2, const float* __restrict__ be2,
    const float* __restrict__ g3, const float* __restrict__ be3,
    const float* __restrict__ g4, const float* __restrict__ be4,
    const float* __restrict__ g5, const float* __restrict__ be5,
    const float* __restrict__ g6, const float* __restrict__ be6)
{
    extern __shared__ float smem[];
    float* IN = smem + SM_IN;
    float* OUT = smem + SM_OUT;
    float* WS = smem + SM_WS;
    float* RED = smem + SM_RED;

    const int s = blockIdx.x;
    const int tid = threadIdx.x;
    const float* t1s = g_t1 + s * 16384;

    // ---- LN1 stats over t1 plane (128x128) ----
    float ls = 0.f, lq = 0.f;
    {
        const float4* t4 = (const float4*)t1s;
        for (int i = tid; i < 4096; i += 512) {
            float4 v = t4[i];
            ls += v.x + v.y + v.z + v.w;
            lq += v.x * v.x + v.y * v.y + v.z * v.z + v.w * v.w;
        }
    }
    bred(ls, lq, 1.f / 16384.f, RED);
    float mu = RED[32], rs = RED[33];

    // zero 68x68 halo buffer, then LN1 + pool -> IN (64x64 interior)
    for (int i = tid; i < 68 * 68; i += 512) IN[i] = 0.f;
    __syncthreads();
    ln_pool<64, 2, 68>(t1s, IN, g1, be1, mu, rs);

    // ---- L2 ----
    ls = lq = 0.f;
    lc_layer<64, 5, 68>(IN, OUT, WS, w2, b2, ls, lq);
    bred(ls, lq, 1.f / 4096.f, RED);
    mu = RED[32]; rs = RED[33];
    ln_apply<64, 2, 68>(OUT, IN, g2, be2, mu, rs);

    // ---- L3 ----
    ls = lq = 0.f;
    lc_layer<64, 5, 68>(IN, OUT, WS, w3, b3, ls, lq);
    bred(ls, lq, 1.f / 4096.f, RED);
    mu = RED[32]; rs = RED[33];
    for (int i = tid; i < 34 * 34; i += 512) IN[i] = 0.f;
    __syncthreads();
    ln_pool<32, 1, 34>(OUT, IN, g3, be3, mu, rs);

    // ---- L4 ----
    ls = lq = 0.f;
    lc_layer<32, 3, 34>(IN, OUT, WS, w4, b4, ls, lq);
    bred(ls, lq, 1.f / 1024.f, RED);
    mu = RED[32]; rs = RED[33];
    ln_apply<32, 1, 34>(OUT, IN, g4, be4, mu, rs);

    // ---- L5 ----
    ls = lq = 0.f;
    lc_layer<32, 3, 34>(IN, OUT, WS, w5, b5, ls, lq);
    bred(ls, lq, 1.f / 1024.f, RED);
    mu = RED[32]; rs = RED[33];
    for (int i = tid; i < 18 * 18; i += 512) IN[i] = 0.f;
    __syncthreads();
    ln_pool<16, 1, 18>(OUT, IN, g5, be5, mu, rs);

    // ---- L6 ----
    ls = lq = 0.f;
    lc_layer<16, 3, 18>(IN, OUT, WS, w6, b6, ls, lq);
    bred(ls, lq, 1.f / 256.f, RED);
    mu = RED[32]; rs = RED[33];
    if (tid < 256) {
        float v = (OUT[tid] - mu) * rs * g6[tid] + be6[tid];
        g_t6[s * 256 + tid] = v;
    }
}

// =====================================================================
// Kernel C: FC GEMM partials. C[64s x 1024o] = X[64x256] @ W^T.
// grid (32 o-tiles, 2 s-tiles, 2 k-halves); tile 32o x 32s, thread 2x2.
// Transposed k-major smem (pad 34) -> conflict-free float2 LDS.
// =====================================================================
__global__ __launch_bounds__(256) void fc_kernel(const float* __restrict__ fcw)
{
    __shared__ float Ws[128 * 34];
    __shared__ float Xs[128 * 34];

    const int tid = threadIdx.x;
    const int o0 = blockIdx.x * 32;
    const int s0 = blockIdx.y * 32;
    const int k0 = blockIdx.z * 128;

    for (int idx = tid; idx < 32 * 128; idx += 256) {
        int o = idx >> 7, k = idx & 127;
        Ws[k * 34 + o] = fcw[(o0 + o) * 256 + k0 + k];
    }
    for (int idx = tid; idx < 32 * 128; idx += 256) {
        int ss = idx >> 7, k = idx & 127;
        Xs[k * 34 + ss] = g_t6[(s0 + ss) * 256 + k0 + k];
    }
    __syncthreads();

    const int oL = (tid & 15) * 2;
    const int sL = (tid >> 4) * 2;
    float a00 = 0.f, a01 = 0.f, a10 = 0.f, a11 = 0.f;
#pragma unroll 4
    for (int k = 0; k < 128; k++) {
        float2 wv = *(const float2*)&Ws[k * 34 + oL];
        float2 xv = *(const float2*)&Xs[k * 34 + sL];
        a00 = fmaf(wv.x, xv.x, a00);
        a10 = fmaf(wv.y, xv.x, a10);
        a01 = fmaf(wv.x, xv.y, a01);
        a11 = fmaf(wv.y, xv.y, a11);
    }
    float* dst = g_fcp[blockIdx.z];
    dst[(s0 + sL) * 1024 + o0 + oL] = a00;
    dst[(s0 + sL) * 1024 + o0 + oL + 1] = a10;
    dst[(s0 + sL + 1) * 1024 + o0 + oL] = a01;
    dst[(s0 + sL + 1) * 1024 + o0 + oL + 1] = a11;
}

// =====================================================================
// Kernel D: combine FC partials + bias, softmax over 1024.
// =====================================================================
__global__ __launch_bounds__(256) void softmax_kernel(
    const float* __restrict__ fcb, float* __restrict__ out)
{
    __shared__ float red[256];
    const int s = blockIdx.x, tid = threadIdx.x;

    float v[4];
    float m = NEG_BIG;
#pragma unroll
    for (int k = 0; k < 4; k++) {
        int o = tid + 256 * k;
        v[k] = g_fcp[0][s * 1024 + o] + g_fcp[1][s * 1024 + o] + fcb[o];
        m = fmaxf(m, v[k]);
    }
    red[tid] = m;
    __syncthreads();
    for (int off = 128; off > 0; off >>= 1) {
        if (tid < off) red[tid] = fmaxf(red[tid], red[tid + off]);
        __syncthreads();
    }
    m = red[0];
    __syncthreads();

    float sum = 0.f;
#pragma unroll
    for (int k = 0; k < 4; k++) {
        v[k] = expf(v[k] - m);
        sum += v[k];
    }
    red[tid] = sum;
    __syncthreads();
    for (int off = 128; off > 0; off >>= 1) {
        if (tid < off) red[tid] += red[tid + off];
        __syncthreads();
    }
    const float inv = 1.f / red[0];
#pragma unroll
    for (int k = 0; k < 4; k++)
        out[s * 1024 + tid + 256 * k] = v[k] * inv;
}

// ---------------- launch ----------------
extern "C" void kernel_launch(void* const* d_in, const int* in_sizes, int n_in,
                              void* d_out, int out_size)
{
    const float* X = (const float*)d_in[0];
    const float* W[6];
    const float* Bi[6];
    const float* G[6];
    const float* Be[6];
    for (int i = 0; i < 6; i++) {
        W[i]  = (const float*)d_in[1 + 4 * i];
        Bi[i] = (const float*)d_in[2 + 4 * i];
        G[i]  = (const float*)d_in[3 + 4 * i];
        Be[i] = (const float*)d_in[4 + 4 * i];
    }
    const float* FCW = (const float*)d_in[25];
    const float* FCB = (const float*)d_in[26];

    float* t1;
    cudaGetSymbolAddress((void**)&t1, g_t1);

    const size_t smemB = SM_TOT * sizeof(float);   // ~137.5 KB
    cudaFuncSetAttribute(fused_kernel,
                         cudaFuncAttributeMaxDynamicSharedMemorySize, (int)smemB);

    l1_kernel<<<dim3(256, 8), 256>>>(X, W[0], Bi[0], t1);

    fused_kernel<<<64, 512, smemB>>>(
        W[1], Bi[1], W[2], Bi[2], W[3], Bi[3], W[4], Bi[4], W[5], Bi[5],
        G[0], Be[0], G[1], Be[1], G[2], Be[2],
        G[3], Be[3], G[4], Be[4], G[5], Be[5]);

    fc_kernel<<<dim3(32, 2, 2), 256>>>(FCW);
    softmax_kernel<<<64, 256>>>(FCB, (float*)d_out);
}

// round 4
// speedup vs baseline: 3.1647x; 1.3101x over previous
#include <cuda_runtime.h>

#define B 64
#define NEG_BIG (-3.402823466e38f)

// ---------------- scratch (device globals; no allocation) ----------------
__device__ float g_t1[B * 128 * 128];
__device__ float g_t6[B * 256];                       // LN6-applied FC input
__device__ __align__(16) float g_fcp[2][B * 1024];    // FC partials
__device__ __align__(16) float g_wT[225536];          // transposed L2..L6 weights

// wT segment bases (floats): w2:0  w3:102400  w4:204800  w5:214016  w6:223232
#define WT2 0
#define WT3 102400
#define WT4 204800
#define WT5 214016
#define WT6 223232
#define WT_TOTAL 225536

// =====================================================================
// Kernel W: transpose LC weights [p][t] -> tap-major grouped layout:
//   region A (t<4G): A[(g*NPOS + p)*4 + j] = w[p*KB + 4g + j]
//   region Bt:       B[p]                  = w[p*KB + 4G]      (KB%4==1)
// =====================================================================
__global__ __launch_bounds__(256) void wt_kernel(
    const float* __restrict__ w2, const float* __restrict__ w3,
    const float* __restrict__ w4, const float* __restrict__ w5,
    const float* __restrict__ w6)
{
    int i = blockIdx.x * 256 + threadIdx.x;
    if (i >= WT_TOTAL) return;
    const float* src;
    int off, NPOS, KB;
    if (i < WT3)      { src = w2; off = i;       NPOS = 4096; KB = 25; }
    else if (i < WT4) { src = w3; off = i - WT3; NPOS = 4096; KB = 25; }
    else if (i < WT5) { src = w4; off = i - WT4; NPOS = 1024; KB = 9;  }
    else if (i < WT6) { src = w5; off = i - WT5; NPOS = 1024; KB = 9;  }
    else              { src = w6; off = i - WT6; NPOS = 256;  KB = 9;  }
    int G4 = (KB / 4) * 4;   // 24 or 8
    int t, p;
    if (off < NPOS * G4) {
        int g = off / (4 * NPOS);
        int r = off % (4 * NPOS);
        p = r >> 2;
        t = 4 * g + (r & 3);
    } else {
        p = off - NPOS * G4;
        t = G4;
    }
    g_wT[i] = src[p * KB + t];
}

// =====================================================================
// Kernel A: L1 locally-connected 7x7 on raw x -> relu -> g_t1  (unchanged)
// =====================================================================
__global__ __launch_bounds__(256) void l1_kernel(
    const float* __restrict__ x, const float* __restrict__ w,
    const float* __restrict__ bias, float* __restrict__ out)
{
    __shared__ float wsh[64 * 49];
    __shared__ float bsh[64];
    __shared__ float xs[4][14][14];

    const int tid = threadIdx.x;
    const int bi = blockIdx.x >> 4, bj = blockIdx.x & 15;
    const int s0 = blockIdx.y * 8;

    for (int idx = tid; idx < 64 * 49; idx += 256) {
        int rr = idx / 392;
        int rem = idx % 392;
        wsh[rr * 392 + rem] = w[((bi * 8 + rr) * 128 + bj * 8) * 49 + rem];
    }
    if (tid < 64) bsh[tid] = bias[(bi * 8 + tid / 8) * 128 + bj * 8 + (tid & 7)];
    __syncthreads();

    const int sl = tid >> 6;
    const int ol = tid & 63;
    const int oi = ol >> 3, oj = ol & 7;

    float wr[49];
#pragma unroll
    for (int t = 0; t < 49; t++) wr[t] = wsh[ol * 49 + t];
    const float br = bsh[ol];

    for (int it = 0; it < 2; it++) {
        const int sbase = s0 + it * 4;
        __syncthreads();
        for (int idx = tid; idx < 4 * 196; idx += 256) {
            int s = idx / 196;
            int rem = idx % 196;
            int pr = rem / 14, pc = rem % 14;
            int r = bi * 8 + pr - 3, c = bj * 8 + pc - 3;
            float v = 0.f;
            if (r >= 0 && r < 128 && c >= 0 && c < 128)
                v = x[((sbase + s) * 128 + r) * 128 + c];
            xs[s][pr][pc] = v;
        }
        __syncthreads();

        float acc = br;
#pragma unroll
        for (int r = 0; r < 7; r++)
#pragma unroll
            for (int c = 0; c < 7; c++)
                acc = fmaf(xs[sl][oi + r][oj + c], wr[r * 7 + c], acc);
        acc = fmaxf(acc, 0.f);
        out[((sbase + sl) * 128 + bi * 8 + oi) * 128 + bj * 8 + oj] = acc;
    }
}

// =====================================================================
// Kernel B: fused L2..L6, block-per-sample, 1024 threads, 35KB static smem.
// Weights read directly from g_wT (coalesced LDG.128, L2-resident).
// =====================================================================
__device__ __forceinline__ void bred(float ls, float lq, float invn, float* RED)
{
#pragma unroll
    for (int o = 16; o > 0; o >>= 1) {
        ls += __shfl_xor_sync(0xffffffffu, ls, o);
        lq += __shfl_xor_sync(0xffffffffu, lq, o);
    }
    const int wid = threadIdx.x >> 5, lane = threadIdx.x & 31;
    if (lane == 0) { RED[wid] = ls; RED[32 + wid] = lq; }
    __syncthreads();
    if (threadIdx.x == 0) {
        float s = 0.f, q = 0.f;
#pragma unroll
        for (int i = 0; i < 32; i++) { s += RED[i]; q += RED[32 + i]; }
        float mu = s * invn;
        float var = q * invn - mu * mu;
        RED[64] = mu;
        RED[65] = rsqrtf(var + 1e-5f);
    }
    __syncthreads();
}

template <int HO, int KK, int STRIDE>
__device__ __forceinline__ void lc_layer_t(
    const float* IN, float* OUT, const float* __restrict__ wT,
    const float* __restrict__ bias, float& ls, float& lq)
{
    constexpr int NPOS = HO * HO;
    constexpr int KB = KK * KK;
    constexpr int G = KB / 4;           // 6 (K=5) or 2 (K=3)
    __syncthreads();                    // IN ready / safe to read
    for (int p0 = 0; p0 < NPOS; p0 += 1024) {
        int p = p0 + threadIdx.x;
        if (p < NPOS) {
            int oi = p / HO, oj = p % HO;
            const float* inb = IN + oi * STRIDE + oj;
            const float4* A = (const float4*)wT;
            float acc = bias[p];
#pragma unroll
            for (int g = 0; g < G; g++) {
                float4 wv = A[g * NPOS + p];
                {
                    constexpr int dummy = 0; (void)dummy;
                }
#pragma unroll
                for (int j = 0; j < 4; j++) {
                    int t = 4 * g + j;
                    int r = t / KK, c = t % KK;
                    float wj = (j == 0) ? wv.x : (j == 1) ? wv.y : (j == 2) ? wv.z : wv.w;
                    acc = fmaf(inb[r * STRIDE + c], wj, acc);
                }
            }
            {   // last tap (KB % 4 == 1)
                constexpr int t = KB - 1;
                constexpr int r = t / KK, c = t % KK;
                acc = fmaf(inb[r * STRIDE + c], wT[4 * G * NPOS + p], acc);
            }
            acc = fmaxf(acc, 0.f);
            OUT[p] = acc;
            ls += acc;
            lq += acc * acc;
        }
    }
}

template <int HO, int PAD, int STRIDE>
__device__ __forceinline__ void ln_apply(
    const float* OUT, float* IN, const float* __restrict__ g,
    const float* __restrict__ be, float mu, float rs)
{
    for (int p = threadIdx.x; p < HO * HO; p += 1024) {
        int i = p / HO, j = p % HO;
        IN[(i + PAD) * STRIDE + j + PAD] = (OUT[p] - mu) * rs * g[p] + be[p];
    }
}

template <int HO, int PAD, int STRIDE>
__device__ __forceinline__ void ln_pool(
    const float* OUT, float* IN, const float* __restrict__ g,
    const float* __restrict__ be, float mu, float rs)
{
    constexpr int H2 = HO * 2;
    for (int p = threadIdx.x; p < HO * HO; p += 1024) {
        int i = p / HO, j = p % HO;
        float m = NEG_BIG;
#pragma unroll
        for (int dr = 0; dr < 2; dr++)
#pragma unroll
            for (int dc = 0; dc < 2; dc++) {
                int idx = (2 * i + dr) * H2 + 2 * j + dc;
                float t = OUT[idx];
                m = fmaxf(m, (t - mu) * rs * g[idx] + be[idx]);
            }
        IN[(i + PAD) * STRIDE + j + PAD] = m;
    }
}

__global__ __launch_bounds__(1024) void fused_kernel(
    const float* __restrict__ b2, const float* __restrict__ b3,
    const float* __restrict__ b4, const float* __restrict__ b5,
    const float* __restrict__ b6,
    const float* __restrict__ g1, const float* __restrict__ be1,
    const float* __restrict__ g2, const float* __restrict__ be2,
    const float* __restrict__ g3, const float* __restrict__ be3,
    const float* __restrict__ g4, const float* __restrict__ be4,
    const float* __restrict__ g5, const float* __restrict__ be5,
    const float* __restrict__ g6, const float* __restrict__ be6)
{
    __shared__ float IN[68 * 68];
    __shared__ float OUT[64 * 64];
    __shared__ float RED[66];

    const int s = blockIdx.x;
    const int tid = threadIdx.x;
    const float* t1s = g_t1 + s * 16384;

    // ---- LN1 stats over t1 plane (128x128) ----
    float ls = 0.f, lq = 0.f;
    {
        const float4* t4 = (const float4*)t1s;
        for (int i = tid; i < 4096; i += 1024) {
            float4 v = t4[i];
            ls += v.x + v.y + v.z + v.w;
            lq += v.x * v.x + v.y * v.y + v.z * v.z + v.w * v.w;
        }
    }
    bred(ls, lq, 1.f / 16384.f, RED);
    float mu = RED[64], rs = RED[65];

    for (int i = tid; i < 68 * 68; i += 1024) IN[i] = 0.f;
    __syncthreads();
    ln_pool<64, 2, 68>(t1s, IN, g1, be1, mu, rs);

    // ---- L2 ----
    ls = lq = 0.f;
    lc_layer_t<64, 5, 68>(IN, OUT, g_wT + WT2, b2, ls, lq);
    bred(ls, lq, 1.f / 4096.f, RED);
    mu = RED[64]; rs = RED[65];
    ln_apply<64, 2, 68>(OUT, IN, g2, be2, mu, rs);

    // ---- L3 ----
    ls = lq = 0.f;
    lc_layer_t<64, 5, 68>(IN, OUT, g_wT + WT3, b3, ls, lq);
    bred(ls, lq, 1.f / 4096.f, RED);
    mu = RED[64]; rs = RED[65];
    for (int i = tid; i < 34 * 34; i += 1024) IN[i] = 0.f;
    __syncthreads();
    ln_pool<32, 1, 34>(OUT, IN, g3, be3, mu, rs);

    // ---- L4 ----
    ls = lq = 0.f;
    lc_layer_t<32, 3, 34>(IN, OUT, g_wT + WT4, b4, ls, lq);
    bred(ls, lq, 1.f / 1024.f, RED);
    mu = RED[64]; rs = RED[65];
    ln_apply<32, 1, 34>(OUT, IN, g4, be4, mu, rs);

    // ---- L5 ----
    ls = lq = 0.f;
    lc_layer_t<32, 3, 34>(IN, OUT, g_wT + WT5, b5, ls, lq);
    bred(ls, lq, 1.f / 1024.f, RED);
    mu = RED[64]; rs = RED[65];
    for (int i = tid; i < 18 * 18; i += 1024) IN[i] = 0.f;
    __syncthreads();
    ln_pool<16, 1, 18>(OUT, IN, g5, be5, mu, rs);

    // ---- L6 ----
    ls = lq = 0.f;
    lc_layer_t<16, 3, 18>(IN, OUT, g_wT + WT6, b6, ls, lq);
    bred(ls, lq, 1.f / 256.f, RED);
    mu = RED[64]; rs = RED[65];
    if (tid < 256) {
        float v = (OUT[tid] - mu) * rs * g6[tid] + be6[tid];
        g_t6[s * 256 + tid] = v;
    }
}

// =====================================================================
// Kernel C: FC GEMM partials. C[64s x 1024o] = X[64x256] @ W^T.
// =====================================================================
__global__ __launch_bounds__(256) void fc_kernel(const float* __restrict__ fcw)
{
    __shared__ float Ws[128 * 34];
    __shared__ float Xs[128 * 34];

    const int tid = threadIdx.x;
    const int o0 = blockIdx.x * 32;
    const int s0 = blockIdx.y * 32;
    const int k0 = blockIdx.z * 128;

    for (int idx = tid; idx < 32 * 128; idx += 256) {
        int o = idx >> 7, k = idx & 127;
        Ws[k * 34 + o] = fcw[(o0 + o) * 256 + k0 + k];
    }
    for (int idx = tid; idx < 32 * 128; idx += 256) {
        int ss = idx >> 7, k = idx & 127;
        Xs[k * 34 + ss] = g_t6[(s0 + ss) * 256 + k0 + k];
    }
    __syncthreads();

    const int oL = (tid & 15) * 2;
    const int sL = (tid >> 4) * 2;
    float a00 = 0.f, a01 = 0.f, a10 = 0.f, a11 = 0.f;
#pragma unroll 4
    for (int k = 0; k < 128; k++) {
        float2 wv = *(const float2*)&Ws[k * 34 + oL];
        float2 xv = *(const float2*)&Xs[k * 34 + sL];
        a00 = fmaf(wv.x, xv.x, a00);
        a10 = fmaf(wv.y, xv.x, a10);
        a01 = fmaf(wv.x, xv.y, a01);
        a11 = fmaf(wv.y, xv.y, a11);
    }
    float* dst = g_fcp[blockIdx.z];
    dst[(s0 + sL) * 1024 + o0 + oL] = a00;
    dst[(s0 + sL) * 1024 + o0 + oL + 1] = a10;
    dst[(s0 + sL + 1) * 1024 + o0 + oL] = a01;
    dst[(s0 + sL + 1) * 1024 + o0 + oL + 1] = a11;
}

// =====================================================================
// Kernel D: combine FC partials + bias, softmax (shuffle reductions).
// 256 threads, 4 consecutive outputs per thread (float4).
// =====================================================================
__global__ __launch_bounds__(256) void softmax_kernel(
    const float* __restrict__ fcb, float* __restrict__ out)
{
    __shared__ float red1[8];
    __shared__ float red2[8];
    const int s = blockIdx.x, tid = threadIdx.x;
    const int wid = tid >> 5, lane = tid & 31;

    const float4* p0 = (const float4*)&g_fcp[0][s * 1024];
    const float4* p1 = (const float4*)&g_fcp[1][s * 1024];
    const float4* pb = (const float4*)fcb;
    float4 a = p0[tid], b = p1[tid], c = pb[tid];
    float4 v;
    v.x = a.x + b.x + c.x;
    v.y = a.y + b.y + c.y;
    v.z = a.z + b.z + c.z;
    v.w = a.w + b.w + c.w;

    float m = fmaxf(fmaxf(v.x, v.y), fmaxf(v.z, v.w));
#pragma unroll
    for (int o = 16; o > 0; o >>= 1) m = fmaxf(m, __shfl_xor_sync(0xffffffffu, m, o));
    if (lane == 0) red1[wid] = m;
    __syncthreads();
    m = red1[0];
#pragma unroll
    for (int i = 1; i < 8; i++) m = fmaxf(m, red1[i]);

    v.x = __expf(v.x - m);
    v.y = __expf(v.y - m);
    v.z = __expf(v.z - m);
    v.w = __expf(v.w - m);
    float sum = v.x + v.y + v.z + v.w;
#pragma unroll
    for (int o = 16; o > 0; o >>= 1) sum += __shfl_xor_sync(0xffffffffu, sum, o);
    if (lane == 0) red2[wid] = sum;
    __syncthreads();
    float tot = 0.f;
#pragma unroll
    for (int i = 0; i < 8; i++) tot += red2[i];
    const float inv = 1.f / tot;

    float4 r;
    r.x = v.x * inv; r.y = v.y * inv; r.z = v.z * inv; r.w = v.w * inv;
    ((float4*)&out[s * 1024])[tid] = r;
}

// ---------------- launch ----------------
extern "C" void kernel_launch(void* const* d_in, const int* in_sizes, int n_in,
                              void* d_out, int out_size)
{
    const float* X = (const float*)d_in[0];
    const float* W[6];
    const float* Bi[6];
    const float* G[6];
    const float* Be[6];
    for (int i = 0; i < 6; i++) {
        W[i]  = (const float*)d_in[1 + 4 * i];
        Bi[i] = (const float*)d_in[2 + 4 * i];
        G[i]  = (const float*)d_in[3 + 4 * i];
        Be[i] = (const float*)d_in[4 + 4 * i];
    }
    const float* FCW = (const float*)d_in[25];
    const float* FCB = (const float*)d_in[26];

    float* t1;
    cudaGetSymbolAddress((void**)&t1, g_t1);

    wt_kernel<<<(WT_TOTAL + 255) / 256, 256>>>(W[1], W[2], W[3], W[4], W[5]);
    l1_kernel<<<dim3(256, 8), 256>>>(X, W[0], Bi[0], t1);

    fused_kernel<<<64, 1024>>>(
        Bi[1], Bi[2], Bi[3], Bi[4], Bi[5],
        G[0], Be[0], G[1], Be[1], G[2], Be[2],
        G[3], Be[3], G[4], Be[4], G[5], Be[5]);

    fc_kernel<<<dim3(32, 2, 2), 256>>>(FCW);
    softmax_kernel<<<64, 256>>>(FCB, (float*)d_out);
}

// round 5
// speedup vs baseline: 4.0246x; 1.2717x over previous
#include <cuda_runtime.h>

#define B 64
#define NEG_BIG (-3.402823466e38f)

// ---------------- scratch (device globals; no allocation) ----------------
__device__ float g_t1[B * 128 * 128];
__device__ float g_t6[B * 256];                       // LN6-applied FC input
__device__ __align__(16) float g_fcp[4][B * 1024];    // FC partials (k-split 4)
__device__ __align__(16) float g_wT[225536];          // transposed L2..L6 weights
__device__ __align__(16) float g_w1T[16384 * 49];     // transposed L1 weights
__device__ float g_sink;

// wT segment bases (floats): w2:0  w3:102400  w4:204800  w5:214016  w6:223232
#define WT2 0
#define WT3 102400
#define WT4 204800
#define WT5 214016
#define WT6 223232
#define WT_TOTAL 225536

// =====================================================================
// Kernel W: transpose L2..L6 weights [p][t] -> tap-major grouped layout
// =====================================================================
__global__ __launch_bounds__(256) void wt_kernel(
    const float* __restrict__ w2, const float* __restrict__ w3,
    const float* __restrict__ w4, const float* __restrict__ w5,
    const float* __restrict__ w6)
{
    int i = blockIdx.x * 256 + threadIdx.x;
    if (i >= WT_TOTAL) return;
    const float* src;
    int off, NPOS, KB;
    if (i < WT3)      { src = w2; off = i;       NPOS = 4096; KB = 25; }
    else if (i < WT4) { src = w3; off = i - WT3; NPOS = 4096; KB = 25; }
    else if (i < WT5) { src = w4; off = i - WT4; NPOS = 1024; KB = 9;  }
    else if (i < WT6) { src = w5; off = i - WT5; NPOS = 1024; KB = 9;  }
    else              { src = w6; off = i - WT6; NPOS = 256;  KB = 9;  }
    int G4 = (KB / 4) * 4;
    int t, p;
    if (off < NPOS * G4) {
        int g = off / (4 * NPOS);
        int r = off % (4 * NPOS);
        p = r >> 2;
        t = 4 * g + (r & 3);
    } else {
        p = off - NPOS * G4;
        t = G4;
    }
    g_wT[i] = src[p * KB + t];
}

// =====================================================================
// Kernel W1: transpose L1 weights (16384 pos x 49 taps) tap-major,
// plus prewarm fcw into L2.
// =====================================================================
#define W1N 16384
#define W1TOT (W1N * 49)          // 802816 -> 3136 blocks
#define W1BLK 3136
#define FCWBLK 1024               // 262144 / 256

__global__ __launch_bounds__(256) void wt1_kernel(
    const float* __restrict__ w1, const float* __restrict__ fcw)
{
    if (blockIdx.x < W1BLK) {
        int i = blockIdx.x * 256 + threadIdx.x;
        if (i >= W1TOT) return;
        int t, p;
        if (i < W1N * 48) {
            int g = i / (4 * W1N);
            int r = i % (4 * W1N);
            p = r >> 2;
            t = 4 * g + (r & 3);
        } else {
            p = i - W1N * 48;
            t = 48;
        }
        g_w1T[i] = w1[p * 49 + t];
    } else {
        int i2 = (blockIdx.x - W1BLK) * 256 + threadIdx.x;
        float v = fcw[i2];
        if (__float_as_uint(v) == 0x7f800001u) g_sink = v;  // keep the load
    }
}

// =====================================================================
// Kernel A: L1 LC 7x7 -> relu -> g_t1.
// Block = 32x16 output tile, thread = 2 adjacent outputs (share taps).
// Grid (32 tiles, 8 sample-splits); weights in regs reused x8 samples.
// =====================================================================
__global__ __launch_bounds__(256, 2) void l1_kernel(
    const float* __restrict__ x, const float* __restrict__ bias,
    float* __restrict__ out)
{
    __shared__ float xs[38 * 23];    // 38 rows x 22 cols (stride 23)

    const int tid = threadIdx.x;
    const int bi = blockIdx.x >> 3;            // 0..3 row-tile
    const int bj = blockIdx.x & 7;             // 0..7 col-tile
    const int s0 = blockIdx.y * 8;
    const int oi = tid >> 3;                   // 0..31
    const int oj2 = (tid & 7) * 2;             // 0..14
    const int gi = bi * 32 + oi;
    const int gj = bj * 16 + oj2;
    const int p0 = gi * 128 + gj;

    // weights for both outputs, coalesced float4 LDG from tap-major layout
    float w0[49], w1r[49];
    const float4* A = (const float4*)g_w1T;
#pragma unroll
    for (int g = 0; g < 12; g++) {
        float4 a0 = A[g * W1N + p0];
        float4 a1 = A[g * W1N + p0 + 1];
        w0[4 * g] = a0.x; w0[4 * g + 1] = a0.y; w0[4 * g + 2] = a0.z; w0[4 * g + 3] = a0.w;
        w1r[4 * g] = a1.x; w1r[4 * g + 1] = a1.y; w1r[4 * g + 2] = a1.z; w1r[4 * g + 3] = a1.w;
    }
    w0[48] = g_w1T[48 * W1N + p0];
    w1r[48] = g_w1T[48 * W1N + p0 + 1];
    const float b0 = bias[p0], b1 = bias[p0 + 1];

    for (int sl = 0; sl < 8; sl++) {
        const int s = s0 + sl;
        __syncthreads();
        // stage 38x22 patch (rows bi*32-3.., cols bj*16-3..), zero OOB
        for (int idx = tid; idx < 38 * 22; idx += 256) {
            int pr = idx / 22, pc = idx % 22;
            int r = bi * 32 + pr - 3, c = bj * 16 + pc - 3;
            float v = 0.f;
            if (r >= 0 && r < 128 && c >= 0 && c < 128)
                v = x[(s * 128 + r) * 128 + c];
            xs[pr * 23 + pc] = v;
        }
        __syncthreads();

        float acc0 = b0, acc1 = b1;
#pragma unroll
        for (int r = 0; r < 7; r++) {
            float xv[8];
#pragma unroll
            for (int c = 0; c < 8; c++) xv[c] = xs[(oi + r) * 23 + oj2 + c];
#pragma unroll
            for (int c = 0; c < 7; c++) {
                acc0 = fmaf(xv[c], w0[r * 7 + c], acc0);
                acc1 = fmaf(xv[c + 1], w1r[r * 7 + c], acc1);
            }
        }
        float* o = &out[(s * 128 + gi) * 128 + gj];
        o[0] = fmaxf(acc0, 0.f);
        o[1] = fmaxf(acc1, 0.f);
    }
}

// =====================================================================
// Kernel B: fused L2..L6, block-per-sample, 1024 threads (unchanged R4).
// =====================================================================
__device__ __forceinline__ void bred(float ls, float lq, float invn, float* RED)
{
#pragma unroll
    for (int o = 16; o > 0; o >>= 1) {
        ls += __shfl_xor_sync(0xffffffffu, ls, o);
        lq += __shfl_xor_sync(0xffffffffu, lq, o);
    }
    const int wid = threadIdx.x >> 5, lane = threadIdx.x & 31;
    if (lane == 0) { RED[wid] = ls; RED[32 + wid] = lq; }
    __syncthreads();
    if (threadIdx.x == 0) {
        float s = 0.f, q = 0.f;
#pragma unroll
        for (int i = 0; i < 32; i++) { s += RED[i]; q += RED[32 + i]; }
        float mu = s * invn;
        float var = q * invn - mu * mu;
        RED[64] = mu;
        RED[65] = rsqrtf(var + 1e-5f);
    }
    __syncthreads();
}

template <int HO, int KK, int STRIDE>
__device__ __forceinline__ void lc_layer_t(
    const float* IN, float* OUT, const float* __restrict__ wT,
    const float* __restrict__ bias, float& ls, float& lq)
{
    constexpr int NPOS = HO * HO;
    constexpr int KB = KK * KK;
    constexpr int G = KB / 4;
    __syncthreads();
    for (int p0 = 0; p0 < NPOS; p0 += 1024) {
        int p = p0 + threadIdx.x;
        if (p < NPOS) {
            int oi = p / HO, oj = p % HO;
            const float* inb = IN + oi * STRIDE + oj;
            const float4* A = (const float4*)wT;
            float acc = bias[p];
#pragma unroll
            for (int g = 0; g < G; g++) {
                float4 wv = A[g * NPOS + p];
#pragma unroll
                for (int j = 0; j < 4; j++) {
                    int t = 4 * g + j;
                    int r = t / KK, c = t % KK;
                    float wj = (j == 0) ? wv.x : (j == 1) ? wv.y : (j == 2) ? wv.z : wv.w;
                    acc = fmaf(inb[r * STRIDE + c], wj, acc);
                }
            }
            {
                constexpr int t = KB - 1;
                constexpr int r = t / KK, c = t % KK;
                acc = fmaf(inb[r * STRIDE + c], wT[4 * G * NPOS + p], acc);
            }
            acc = fmaxf(acc, 0.f);
            OUT[p] = acc;
            ls += acc;
            lq += acc * acc;
        }
    }
}

template <int HO, int PAD, int STRIDE>
__device__ __forceinline__ void ln_apply(
    const float* OUT, float* IN, const float* __restrict__ g,
    const float* __restrict__ be, float mu, float rs)
{
    for (int p = threadIdx.x; p < HO * HO; p += 1024) {
        int i = p / HO, j = p % HO;
        IN[(i + PAD) * STRIDE + j + PAD] = (OUT[p] - mu) * rs * g[p] + be[p];
    }
}

template <int HO, int PAD, int STRIDE>
__device__ __forceinline__ void ln_pool(
    const float* OUT, float* IN, const float* __restrict__ g,
    const float* __restrict__ be, float mu, float rs)
{
    constexpr int H2 = HO * 2;
    for (int p = threadIdx.x; p < HO * HO; p += 1024) {
        int i = p / HO, j = p % HO;
        float m = NEG_BIG;
#pragma unroll
        for (int dr = 0; dr < 2; dr++)
#pragma unroll
            for (int dc = 0; dc < 2; dc++) {
                int idx = (2 * i + dr) * H2 + 2 * j + dc;
                float t = OUT[idx];
                m = fmaxf(m, (t - mu) * rs * g[idx] + be[idx]);
            }
        IN[(i + PAD) * STRIDE + j + PAD] = m;
    }
}

__global__ __launch_bounds__(1024) void fused_kernel(
    const float* __restrict__ b2, const float* __restrict__ b3,
    const float* __restrict__ b4, const float* __restrict__ b5,
    const float* __restrict__ b6,
    const float* __restrict__ g1, const float* __restrict__ be1,
    const float* __restrict__ g2, const float* __restrict__ be2,
    const float* __restrict__ g3, const float* __restrict__ be3,
    const float* __restrict__ g4, const float* __restrict__ be4,
    const float* __restrict__ g5, const float* __restrict__ be5,
    const float* __restrict__ g6, const float* __restrict__ be6)
{
    __shared__ float IN[68 * 68];
    __shared__ float OUT[64 * 64];
    __shared__ float RED[66];

    const int s = blockIdx.x;
    const int tid = threadIdx.x;
    const float* t1s = g_t1 + s * 16384;

    float ls = 0.f, lq = 0.f;
    {
        const float4* t4 = (const float4*)t1s;
        for (int i = tid; i < 4096; i += 1024) {
            float4 v = t4[i];
            ls += v.x + v.y + v.z + v.w;
            lq += v.x * v.x + v.y * v.y + v.z * v.z + v.w * v.w;
        }
    }
    bred(ls, lq, 1.f / 16384.f, RED);
    float mu = RED[64], rs = RED[65];

    for (int i = tid; i < 68 * 68; i += 1024) IN[i] = 0.f;
    __syncthreads();
    ln_pool<64, 2, 68>(t1s, IN, g1, be1, mu, rs);

    ls = lq = 0.f;
    lc_layer_t<64, 5, 68>(IN, OUT, g_wT + WT2, b2, ls, lq);
    bred(ls, lq, 1.f / 4096.f, RED);
    mu = RED[64]; rs = RED[65];
    ln_apply<64, 2, 68>(OUT, IN, g2, be2, mu, rs);

    ls = lq = 0.f;
    lc_layer_t<64, 5, 68>(IN, OUT, g_wT + WT3, b3, ls, lq);
    bred(ls, lq, 1.f / 4096.f, RED);
    mu = RED[64]; rs = RED[65];
    for (int i = tid; i < 34 * 34; i += 1024) IN[i] = 0.f;
    __syncthreads();
    ln_pool<32, 1, 34>(OUT, IN, g3, be3, mu, rs);

    ls = lq = 0.f;
    lc_layer_t<32, 3, 34>(IN, OUT, g_wT + WT4, b4, ls, lq);
    bred(ls, lq, 1.f / 1024.f, RED);
    mu = RED[64]; rs = RED[65];
    ln_apply<32, 1, 34>(OUT, IN, g4, be4, mu, rs);

    ls = lq = 0.f;
    lc_layer_t<32, 3, 34>(IN, OUT, g_wT + WT5, b5, ls, lq);
    bred(ls, lq, 1.f / 1024.f, RED);
    mu = RED[64]; rs = RED[65];
    for (int i = tid; i < 18 * 18; i += 1024) IN[i] = 0.f;
    __syncthreads();
    ln_pool<16, 1, 18>(OUT, IN, g5, be5, mu, rs);

    ls = lq = 0.f;
    lc_layer_t<16, 3, 18>(IN, OUT, g_wT + WT6, b6, ls, lq);
    bred(ls, lq, 1.f / 256.f, RED);
    mu = RED[64]; rs = RED[65];
    if (tid < 256) {
        float v = (OUT[tid] - mu) * rs * g6[tid] + be6[tid];
        g_t6[s * 256 + tid] = v;
    }
}

// =====================================================================
// Kernel C: FC GEMM partials, k-split 4. grid (32, 2, 4) = 256 blocks.
// =====================================================================
__global__ __launch_bounds__(256) void fc_kernel(const float* __restrict__ fcw)
{
    __shared__ float Ws[64 * 34];
    __shared__ float Xs[64 * 34];

    const int tid = threadIdx.x;
    const int o0 = blockIdx.x * 32;
    const int s0 = blockIdx.y * 32;
    const int k0 = blockIdx.z * 64;

    for (int idx = tid; idx < 32 * 64; idx += 256) {
        int o = idx >> 6, k = idx & 63;
        Ws[k * 34 + o] = fcw[(o0 + o) * 256 + k0 + k];
    }
    for (int idx = tid; idx < 32 * 64; idx += 256) {
        int ss = idx >> 6, k = idx & 63;
        Xs[k * 34 + ss] = g_t6[(s0 + ss) * 256 + k0 + k];
    }
    __syncthreads();

    const int oL = (tid & 15) * 2;
    const int sL = (tid >> 4) * 2;
    float a00 = 0.f, a01 = 0.f, a10 = 0.f, a11 = 0.f;
#pragma unroll 8
    for (int k = 0; k < 64; k++) {
        float2 wv = *(const float2*)&Ws[k * 34 + oL];
        float2 xv = *(const float2*)&Xs[k * 34 + sL];
        a00 = fmaf(wv.x, xv.x, a00);
        a10 = fmaf(wv.y, xv.x, a10);
        a01 = fmaf(wv.x, xv.y, a01);
        a11 = fmaf(wv.y, xv.y, a11);
    }
    float* dst = g_fcp[blockIdx.z];
    dst[(s0 + sL) * 1024 + o0 + oL] = a00;
    dst[(s0 + sL) * 1024 + o0 + oL + 1] = a10;
    dst[(s0 + sL + 1) * 1024 + o0 + oL] = a01;
    dst[(s0 + sL + 1) * 1024 + o0 + oL + 1] = a11;
}

// =====================================================================
// Kernel D: combine 4 FC partials + bias, softmax (shuffle reductions).
// =====================================================================
__global__ __launch_bounds__(256) void softmax_kernel(
    const float* __restrict__ fcb, float* __restrict__ out)
{
    __shared__ float red1[8];
    __shared__ float red2[8];
    const int s = blockIdx.x, tid = threadIdx.x;
    const int wid = tid >> 5, lane = tid & 31;

    const float4* p0 = (const float4*)&g_fcp[0][s * 1024];
    const float4* p1 = (const float4*)&g_fcp[1][s * 1024];
    const float4* p2 = (const float4*)&g_fcp[2][s * 1024];
    const float4* p3 = (const float4*)&g_fcp[3][s * 1024];
    const float4* pb = (const float4*)fcb;
    float4 a = p0[tid], b = p1[tid], c = p2[tid], d = p3[tid], e = pb[tid];
    float4 v;
    v.x = a.x + b.x + c.x + d.x + e.x;
    v.y = a.y + b.y + c.y + d.y + e.y;
    v.z = a.z + b.z + c.z + d.z + e.z;
    v.w = a.w + b.w + c.w + d.w + e.w;

    float m = fmaxf(fmaxf(v.x, v.y), fmaxf(v.z, v.w));
#pragma unroll
    for (int o = 16; o > 0; o >>= 1) m = fmaxf(m, __shfl_xor_sync(0xffffffffu, m, o));
    if (lane == 0) red1[wid] = m;
    __syncthreads();
    m = red1[0];
#pragma unroll
    for (int i = 1; i < 8; i++) m = fmaxf(m, red1[i]);

    v.x = __expf(v.x - m);
    v.y = __expf(v.y - m);
    v.z = __expf(v.z - m);
    v.w = __expf(v.w - m);
    float sum = v.x + v.y + v.z + v.w;
#pragma unroll
    for (int o = 16; o > 0; o >>= 1) sum += __shfl_xor_sync(0xffffffffu, sum, o);
    if (lane == 0) red2[wid] = sum;
    __syncthreads();
    float tot = 0.f;
#pragma unroll
    for (int i = 0; i < 8; i++) tot += red2[i];
    const float inv = 1.f / tot;

    float4 r;
    r.x = v.x * inv; r.y = v.y * inv; r.z = v.z * inv; r.w = v.w * inv;
    ((float4*)&out[s * 1024])[tid] = r;
}

// ---------------- launch ----------------
extern "C" void kernel_launch(void* const* d_in, const int* in_sizes, int n_in,
                              void* d_out, int out_size)
{
    const float* X = (const float*)d_in[0];
    const float* W[6];
    const float* Bi[6];
    const float* G[6];
    const float* Be[6];
    for (int i = 0; i < 6; i++) {
        W[i]  = (const float*)d_in[1 + 4 * i];
        Bi[i] = (const float*)d_in[2 + 4 * i];
        G[i]  = (const float*)d_in[3 + 4 * i];
        Be[i] = (const float*)d_in[4 + 4 * i];
    }
    const float* FCW = (const float*)d_in[25];
    const float* FCB = (const float*)d_in[26];

    float* t1;
    cudaGetSymbolAddress((void**)&t1, g_t1);

    wt_kernel<<<(WT_TOTAL + 255) / 256, 256>>>(W[1], W[2], W[3], W[4], W[5]);
    wt1_kernel<<<W1BLK + FCWBLK, 256>>>(W[0], FCW);

    l1_kernel<<<dim3(32, 8), 256>>>(X, Bi[0], t1);

    fused_kernel<<<64, 1024>>>(
        Bi[1], Bi[2], Bi[3], Bi[4], Bi[5],
        G[0], Be[0], G[1], Be[1], G[2], Be[2],
        G[3], Be[3], G[4], Be[4], G[5], Be[5]);

    fc_kernel<<<dim3(32, 2, 4), 256>>>(FCW);
    softmax_kernel<<<64, 256>>>(FCB, (float*)d_out);
}